// round 17
// baseline (speedup 1.0000x reference)
#include <cuda_runtime.h>
#include <cuda_bf16.h>
#include <math.h>
#include <stdint.h>

#define B  4096
#define D  1792
#define NC 3000
#define NM 7000
#define NF 13000
#define NTOT (NC + NM + NF)

// padded (tile-128) class counts for the transposed weight buffers
#define NPC 3072
#define NPM 7168
#define NPF 13056
#define SEC_C 0
#define SEC_M 3072
#define SEC_F 10240
#define NPTOT 23296
#define NSTRIP (NPTOT / 128)      // 182 n-tiles
#define NSUB   (NSTRIP * 4)       // 728 sub-strips of 32 cols

// sub-strip ranges per head (4 per 128-col tile)
#define SUB_C0 0
#define SUB_CN 96                 // 24 tiles * 4
#define SUB_M0 96
#define SUB_MN 224                // 56 tiles * 4
#define SUB_F0 320
#define SUB_FN 408                // 102 tiles * 4

#define OFF_C ((size_t)0)
#define OFF_M ((size_t)B * NC)
#define OFF_F (OFF_M + (size_t)B * NM)

// ---- device scratch (no runtime allocation allowed) ----
__device__ __nv_bfloat16 g_logits[(size_t)B * NTOT];   // ~188 MB (bf16)
__device__ __nv_bfloat16 g_A_hi[(size_t)B * D];
__device__ __nv_bfloat16 g_Wt_hi[(size_t)NPTOT * D];   // transposed [n][k]
__device__ float g_pm[(size_t)B * NSUB];               // [b][sub] row max
__device__ float g_ps[(size_t)B * NSUB];               // [b][sub] row sumexp
__device__ float g_label_xyz[B * 3];
__device__ float g_part_xyz[NTOT * 3];
__device__ int   g_label_idx[3 * B];
__device__ float g_nll[B];
__device__ int   g_counts[5];

// ============================================================
// helpers
// ============================================================
__device__ __forceinline__ uint32_t smem_to_u32(const void* p) {
    uint32_t a;
    asm("{ .reg .u64 t; cvta.to.shared.u64 t, %1; cvt.u32.u64 %0, t; }"
        : "=r"(a) : "l"(p));
    return a;
}
#define CP_ASYNC16(sm, gp) \
    asm volatile("cp.async.cg.shared.global [%0], [%1], 16;" :: "r"(sm), "l"(gp) : "memory")

__device__ __forceinline__ void ldsm_x4(uint32_t* r, uint32_t addr) {
    asm volatile("ldmatrix.sync.aligned.m8n8.x4.shared.b16 {%0,%1,%2,%3}, [%4];"
        : "=r"(r[0]), "=r"(r[1]), "=r"(r[2]), "=r"(r[3]) : "r"(addr));
}
__device__ __forceinline__ void mma_bf16(float* d, const uint32_t* a, const uint32_t* b) {
    asm volatile("mma.sync.aligned.m16n8k16.row.col.f32.bf16.bf16.f32 "
        "{%0,%1,%2,%3}, {%4,%5,%6,%7}, {%8,%9}, {%0,%1,%2,%3};"
        : "+f"(d[0]), "+f"(d[1]), "+f"(d[2]), "+f"(d[3])
        : "r"(a[0]), "r"(a[1]), "r"(a[2]), "r"(a[3]), "r"(b[0]), "r"(b[1]));
}
__device__ __forceinline__ uint32_t pack_bf16x2(float x, float y) {
    __nv_bfloat16 bx = __float2bfloat16(x), by = __float2bfloat16(y);
    return ((uint32_t)__bfloat16_as_ushort(by) << 16) | __bfloat16_as_ushort(bx);
}
// exact bf16x2 -> float unpack (bit ops only)
__device__ __forceinline__ float bf_lo(uint32_t p) { return __uint_as_float(p << 16); }
__device__ __forceinline__ float bf_hi(uint32_t p) { return __uint_as_float(p & 0xffff0000u); }

// ============================================================
// Kernel: precompute unit vectors, zero counters
// ============================================================
__global__ void k_init(const float* __restrict__ labels,
                       const float* __restrict__ cpart,
                       const float* __restrict__ mpart,
                       const float* __restrict__ fpart)
{
    int t = blockIdx.x * blockDim.x + threadIdx.x;
    const float RADF = 0.017453292519943295f;
    if (t < B) {
        float la = labels[t * 2] * RADF, lo = labels[t * 2 + 1] * RADF;
        float cl = cosf(la);
        g_label_xyz[t * 3 + 0] = cl * cosf(lo);
        g_label_xyz[t * 3 + 1] = cl * sinf(lo);
        g_label_xyz[t * 3 + 2] = sinf(la);
    }
    if (t < NTOT) {
        const float* src;
        if (t < NC)            src = cpart + (size_t)t * 2;
        else if (t < NC + NM)  src = mpart + (size_t)(t - NC) * 2;
        else                   src = fpart + (size_t)(t - NC - NM) * 2;
        float la = src[0] * RADF, lo = src[1] * RADF;
        float cl = cosf(la);
        g_part_xyz[t * 3 + 0] = cl * cosf(lo);
        g_part_xyz[t * 3 + 1] = cl * sinf(lo);
        g_part_xyz[t * 3 + 2] = sinf(la);
    }
    if (t < 5) g_counts[t] = 0;
}

// ============================================================
// Kernel: label index — one WARP per (head, b), shfl argmax reduce
// ============================================================
__global__ __launch_bounds__(256)
void k_labelidx()
{
    int gw = blockIdx.x * 8 + (threadIdx.x >> 5);
    if (gw >= 3 * B) return;
    int lane = threadIdx.x & 31;
    int head = gw >> 12;
    int b    = gw & (B - 1);
    int base, n;
    if (head == 0)      { base = 0;       n = NC; }
    else if (head == 1) { base = NC;      n = NM; }
    else                { base = NC + NM; n = NF; }
    float lx = g_label_xyz[b * 3 + 0];
    float ly = g_label_xyz[b * 3 + 1];
    float lz = g_label_xyz[b * 3 + 2];
    const float* P = g_part_xyz + (size_t)base * 3;
    float best = -2.0f; int bi = 0x7fffffff;
    for (int i = lane; i < n; i += 32) {
        float d = lx * P[i * 3] + ly * P[i * 3 + 1] + lz * P[i * 3 + 2];
        if (d > best || (d == best && i < bi)) { best = d; bi = i; }
    }
#pragma unroll
    for (int off = 16; off > 0; off >>= 1) {
        float ob = __shfl_down_sync(0xffffffffu, best, off);
        int   oi = __shfl_down_sync(0xffffffffu, bi,   off);
        if (ob > best || (ob == best && oi < bi)) { best = ob; bi = oi; }
    }
    if (lane == 0) g_label_idx[head * B + b] = bi;
}

// ============================================================
// Kernel: convert features -> bf16, float4 -> uint2
// ============================================================
__global__ void k_convA(const float4* __restrict__ A)
{
    int t = blockIdx.x * blockDim.x + threadIdx.x;
    if (t >= (B * D) / 4) return;
    float4 v = A[t];
    uint2 hp;
    hp.x = pack_bf16x2(v.x, v.y);
    hp.y = pack_bf16x2(v.z, v.w);
    ((uint2*)g_A_hi)[t] = hp;
}

// ============================================================
// Kernel: fused transpose+convert for ALL heads, vectorized:
// W [D][N] -> Wt [NPTOT][D] bf16 (zero pad). 64x64 tiles,
// float4 loads, uint2 (4xbf16) stores.
// ============================================================
__global__ __launch_bounds__(256)
void k_convW(const float* __restrict__ cw,
             const float* __restrict__ mw,
             const float* __restrict__ fw)
{
    __shared__ float t[64][65];
    int k0  = blockIdx.x * 64;
    int ng0 = blockIdx.y * 64;
    const float* W; int N, sec;
    if (ng0 < SEC_M)      { W = cw; N = NC; sec = SEC_C; }
    else if (ng0 < SEC_F) { W = mw; N = NM; sec = SEC_M; }
    else                  { W = fw; N = NF; sec = SEC_F; }
    int n0 = ng0 - sec;
    const int tx = threadIdx.x & 15;
    const int ty = threadIdx.x >> 4;
#pragma unroll
    for (int j = 0; j < 4; j++) {
        int k = k0 + ty + j * 16;
        int n = n0 + tx * 4;
        float4 v = make_float4(0.f, 0.f, 0.f, 0.f);
        if (n < N) v = *(const float4*)&W[(size_t)k * N + n];
        t[ty + j * 16][tx * 4 + 0] = v.x;
        t[ty + j * 16][tx * 4 + 1] = v.y;
        t[ty + j * 16][tx * 4 + 2] = v.z;
        t[ty + j * 16][tx * 4 + 3] = v.w;
    }
    __syncthreads();
#pragma unroll
    for (int j = 0; j < 4; j++) {
        int nl = ty + j * 16;
        int n  = ng0 + nl;
        uint2 o;
        o.x = pack_bf16x2(t[tx * 4 + 0][nl], t[tx * 4 + 1][nl]);
        o.y = pack_bf16x2(t[tx * 4 + 2][nl], t[tx * 4 + 3][nl]);
        *(uint2*)&g_Wt_hi[(size_t)n * D + k0 + tx * 4] = o;
    }
}

// ============================================================
// Pure-bf16 GEMM, 2 CTAs/SM: 128x128 tile, warp tile 64x32,
// 256 threads, BK=64, 3-stage pipe, ONE barrier/chunk, SW128.
// Launched per m-half (mbase). Epilogue: bf16 logits store +
// per-sub-strip (32-col) LSE partials.
// ============================================================
#define BM 128
#define BN 128
#define BK 64
#define ST_A 0
#define ST_B 16384
#define STAGE_BYTES 32768
#define NSTG 3
#define GEMM_SMEM (NSTG * STAGE_BYTES)     // 96 KB -> 2 CTAs/SM
#define NKC (D / BK)              // 28
#define GRID_MH ((B / BM) / 2)    // 16 m-tiles per half
#define GRID_N NSTRIP             // 182 = 14 * 13
#define SUPER_N 13
#define A_GSTRIDE (32 * D * 2)
#define SW_STRIDE (32 * 128)

__global__ __launch_bounds__(256, 2)
void k_mmagemm(const float* __restrict__ cb, const float* __restrict__ mb,
               const float* __restrict__ fb, int mbase)
{
    extern __shared__ __align__(1024) char smem[];
    uint32_t sb = smem_to_u32(smem);
    const int tid  = threadIdx.x;
    const int wid  = tid >> 5;
    const int lane = tid & 31;
    const int wm   = wid >> 2;
    const int wn   = wid & 3;

    // supertile rasterization: 16 m x 13 n per supertile (per half)
    const int gid = blockIdx.x;
    const int sy  = gid / (GRID_MH * SUPER_N);
    const int r   = gid % (GRID_MH * SUPER_N);
    const int mx  = r / SUPER_N;
    const int ny  = sy * SUPER_N + (r % SUPER_N);
    const int m0  = mbase + mx * BM;
    const int n0  = ny * BN;

    int N, sec; size_t outOff; const float* bias;
    if (n0 < SEC_M)      { N = NC; sec = SEC_C; outOff = OFF_C; bias = cb; }
    else if (n0 < SEC_F) { N = NM; sec = SEC_M; outOff = OFF_M; bias = mb; }
    else                 { N = NF; sec = SEC_F; outOff = OFF_F; bias = fb; }
    const int nloc0 = n0 - sec;

    const int crow = tid >> 3, cseg = tid & 7;
    const uint32_t cSw0 = (uint32_t)(crow * 128 + ((cseg * 16) ^ ((crow & 7) << 4)));
    const uint32_t cGo0 = (uint32_t)((crow * D + cseg * 8) * 2);
    const char* Ahp = (const char*)(g_A_hi  + (size_t)m0 * D);
    const char* Bhp = (const char*)(g_Wt_hi + (size_t)n0 * D);

    const int arow = wm * 64 + (lane & 7) + ((lane >> 3) & 1) * 8;
    const uint32_t aTerm0 = (uint32_t)(arow * 128);
    const uint32_t aXor   = (uint32_t)((arow & 7) << 4);
    const uint32_t aCSel  = ((lane >> 4) & 1) * 16;
    const int brow = wn * 32 + (lane & 7) + ((lane >> 4) & 1) * 8;
    const uint32_t bTerm0 = (uint32_t)(brow * 128);
    const uint32_t bXor   = (uint32_t)((brow & 7) << 4);
    const uint32_t bCSel  = ((lane >> 3) & 1) * 16;

    float acc[4][4][4];
#pragma unroll
    for (int i = 0; i < 4; i++)
#pragma unroll
        for (int j = 0; j < 4; j++)
#pragma unroll
            for (int k = 0; k < 4; k++) acc[i][j][k] = 0.f;

#define ISSUE(c) do { \
        int _c = (c); \
        uint32_t kb2 = (uint32_t)(_c * BK * 2); \
        uint32_t st = sb + (uint32_t)(_c % NSTG) * STAGE_BYTES; \
        _Pragma("unroll") \
        for (int i = 0; i < 4; i++) { \
            CP_ASYNC16(st + ST_A + cSw0 + i * SW_STRIDE, Ahp + kb2 + cGo0 + i * A_GSTRIDE); \
            CP_ASYNC16(st + ST_B + cSw0 + i * SW_STRIDE, Bhp + kb2 + cGo0 + i * A_GSTRIDE); \
        } \
        asm volatile("cp.async.commit_group;" ::: "memory"); \
    } while (0)

    ISSUE(0);
    ISSUE(1);

    for (int c = 0; c < NKC; c++) {
        if (c + 1 < NKC) asm volatile("cp.async.wait_group 1;" ::: "memory");
        else             asm volatile("cp.async.wait_group 0;" ::: "memory");
        __syncthreads();
        if (c + 2 < NKC) ISSUE(c + 2);

        uint32_t st = sb + (uint32_t)(c % NSTG) * STAGE_BYTES;
#pragma unroll
        for (int ks = 0; ks < 4; ks++) {
            const uint32_t kb = (uint32_t)(ks * 32);
            uint32_t a[4][4], bh[2][4];
            const uint32_t aOff = (kb + aCSel) ^ aXor;
            const uint32_t bOff = (kb + bCSel) ^ bXor;
#pragma unroll
            for (int mt = 0; mt < 4; mt++)
                ldsm_x4(a[mt], st + ST_A + aTerm0 + mt * 2048 + aOff);
#pragma unroll
            for (int np = 0; np < 2; np++)
                ldsm_x4(bh[np], st + ST_B + bTerm0 + np * 2048 + bOff);
#pragma unroll
            for (int mt = 0; mt < 4; mt++)
#pragma unroll
                for (int nt = 0; nt < 4; nt++)
                    mma_bf16(acc[mt][nt], a[mt], &bh[nt >> 1][(nt & 1) * 2]);
        }
    }
#undef ISSUE

    // ---- epilogue: bias + store bf16 logits + per-sub-strip LSE partials ----
    __nv_bfloat16* out = g_logits + outOff;
    const int sub = ny * 4 + wn;
    const int rbase = m0 + wm * 64 + (lane >> 2);
    const int cb0 = nloc0 + wn * 32 + (lane & 3) * 2;
#pragma unroll
    for (int mt = 0; mt < 4; mt++) {
        int r0 = rbase + mt * 16;
        float v0[8], v1[8];
#pragma unroll
        for (int nt = 0; nt < 4; nt++) {
            int col = cb0 + nt * 8;
            bool ok = (col < N);
            float bx = 0.f, by = 0.f;
            if (ok) { bx = bias[col]; by = bias[col + 1]; }
            float a0 = acc[mt][nt][0] + bx;
            float a1 = acc[mt][nt][1] + by;
            float a2 = acc[mt][nt][2] + bx;
            float a3 = acc[mt][nt][3] + by;
            if (ok) {
                *(uint32_t*)&out[(size_t)r0 * N + col]       = pack_bf16x2(a0, a1);
                *(uint32_t*)&out[(size_t)(r0 + 8) * N + col] = pack_bf16x2(a2, a3);
            }
            v0[nt * 2 + 0] = ok ? a0 : -1e30f;
            v0[nt * 2 + 1] = ok ? a1 : -1e30f;
            v1[nt * 2 + 0] = ok ? a2 : -1e30f;
            v1[nt * 2 + 1] = ok ? a3 : -1e30f;
        }
        float m0v = v0[0], m1v = v1[0];
#pragma unroll
        for (int j = 1; j < 8; j++) { m0v = fmaxf(m0v, v0[j]); m1v = fmaxf(m1v, v1[j]); }
#pragma unroll
        for (int o = 1; o <= 2; o <<= 1) {
            m0v = fmaxf(m0v, __shfl_xor_sync(0xffffffffu, m0v, o));
            m1v = fmaxf(m1v, __shfl_xor_sync(0xffffffffu, m1v, o));
        }
        float s0 = 0.f, s1 = 0.f;
#pragma unroll
        for (int j = 0; j < 8; j++) {
            s0 += __expf(v0[j] - m0v);
            s1 += __expf(v1[j] - m1v);
        }
#pragma unroll
        for (int o = 1; o <= 2; o <<= 1) {
            s0 += __shfl_xor_sync(0xffffffffu, s0, o);
            s1 += __shfl_xor_sync(0xffffffffu, s1, o);
        }
        if ((lane & 3) == 0) {
            g_pm[(size_t)r0 * NSUB + sub]       = m0v;
            g_ps[(size_t)r0 * NSUB + sub]       = s0;
            g_pm[(size_t)(r0 + 8) * NSUB + sub] = m1v;
            g_ps[(size_t)(r0 + 8) * NSUB + sub] = s1;
        }
    }
}

// ============================================================
// Tail (512 threads, per b-half): combine LSE partials, NLL,
// hierarchical argmax. sC stored as bf16 (exact) -> 34000 B smem.
// ============================================================
#define TAIL_SMEM (NM * 4 + NC * 2)
#define TAIL_T 512

__global__ __launch_bounds__(TAIL_T)
void k_tail(const float* __restrict__ labels,
            const float* __restrict__ fpart,
            const int*   __restrict__ fparents,
            const int*   __restrict__ mparents, int bbase)
{
    extern __shared__ float sh[];
    float* tM = sh;                                   // NM floats
    __nv_bfloat16* sCb = (__nv_bfloat16*)(sh + NM);   // NC bf16
    __shared__ float lseS[3];
    __shared__ float rf[16];
    __shared__ int   ri[16];

    int b = bbase + blockIdx.x, tid = threadIdx.x;
    int lane = tid & 31, wid = tid >> 5;
    const __nv_bfloat16* Cv = g_logits + OFF_C + (size_t)b * NC;
    const __nv_bfloat16* Mv = g_logits + OFF_M + (size_t)b * NM;
    const __nv_bfloat16* Fv = g_logits + OFF_F + (size_t)b * NF;
    const uint2* Cv4 = (const uint2*)Cv;
    const uint2* Mv4 = (const uint2*)Mv;
    const uint2* Fv4 = (const uint2*)Fv;
    const float* pmRow = g_pm + (size_t)b * NSUB;
    const float* psRow = g_ps + (size_t)b * NSUB;

    for (int i = tid; i < NC / 4; i += TAIL_T)
        ((uint2*)sCb)[i] = Cv4[i];

    // warps 0..2: combine per-sub-strip LSE partials for head wid (2-pass)
    if (wid < 3) {
        int base = (wid == 0) ? SUB_C0 : (wid == 1) ? SUB_M0 : SUB_F0;
        int cnt  = (wid == 0) ? SUB_CN : (wid == 1) ? SUB_MN : SUB_FN;
        float m = -3.402823466e38f;
        for (int i = lane; i < cnt; i += 32)
            m = fmaxf(m, pmRow[base + i]);
#pragma unroll
        for (int o = 16; o > 0; o >>= 1)
            m = fmaxf(m, __shfl_xor_sync(0xffffffffu, m, o));
        float s = 0.f;
        for (int i = lane; i < cnt; i += 32)
            s += psRow[base + i] * __expf(pmRow[base + i] - m);
#pragma unroll
        for (int o = 16; o > 0; o >>= 1)
            s += __shfl_xor_sync(0xffffffffu, s, o);
        if (lane == 0) lseS[wid] = m + logf(s);
    }
    __syncthreads();

    // t[m] = Mv[m] + sC[mparents[m]]  (4 per iter)
    const int4* mp4 = (const int4*)mparents;
    for (int i = tid; i < NM / 4; i += TAIL_T) {
        uint2 p = Mv4[i];
        int4 mp = mp4[i];
        tM[4 * i + 0] = bf_lo(p.x) + __bfloat162float(sCb[mp.x]);
        tM[4 * i + 1] = bf_hi(p.x) + __bfloat162float(sCb[mp.y]);
        tM[4 * i + 2] = bf_lo(p.y) + __bfloat162float(sCb[mp.z]);
        tM[4 * i + 3] = bf_hi(p.y) + __bfloat162float(sCb[mp.w]);
    }
    __syncthreads();

    // hierarchical argmax over fine classes (4 per iter)
    const int4* fp4 = (const int4*)fparents;
    float best = -3.402823466e38f; int bi = 0x7fffffff;
    for (int i = tid; i < NF / 4; i += TAIL_T) {
        uint2 p = Fv4[i];
        int4 fp = fp4[i];
        float s0 = bf_lo(p.x) + tM[fp.x];
        float s1 = bf_hi(p.x) + tM[fp.y];
        float s2 = bf_lo(p.y) + tM[fp.z];
        float s3 = bf_hi(p.y) + tM[fp.w];
        if (s0 > best) { best = s0; bi = 4 * i; }
        if (s1 > best) { best = s1; bi = 4 * i + 1; }
        if (s2 > best) { best = s2; bi = 4 * i + 2; }
        if (s3 > best) { best = s3; bi = 4 * i + 3; }
    }
#pragma unroll
    for (int o = 16; o > 0; o >>= 1) {
        float ob = __shfl_xor_sync(0xffffffffu, best, o);
        int   oi = __shfl_xor_sync(0xffffffffu, bi,   o);
        if (ob > best || (ob == best && oi < bi)) { best = ob; bi = oi; }
    }
    if (lane == 0) { rf[wid] = best; ri[wid] = bi; }
    __syncthreads();

    if (tid == 0) {
        float bb = rf[0]; int pp = ri[0];
#pragma unroll
        for (int j = 1; j < 16; j++) {
            if (rf[j] > bb || (rf[j] == bb && ri[j] < pp)) { bb = rf[j]; pp = ri[j]; }
        }
        int liC = g_label_idx[b];
        int liM = g_label_idx[B + b];
        int liF = g_label_idx[2 * B + b];
        g_nll[b] = (lseS[0] - __bfloat162float(sCb[liC]))
                 + (lseS[1] - __bfloat162float(Mv[liM]))
                 + (lseS[2] - __bfloat162float(Fv[liF]));

        const float RADF = 0.017453292519943295f;
        float lat1 = labels[b * 2]      * RADF;
        float lon1 = labels[b * 2 + 1]  * RADF;
        float lat2 = fpart[pp * 2]      * RADF;
        float lon2 = fpart[pp * 2 + 1]  * RADF;
        float sdlat = sinf((lat2 - lat1) * 0.5f);
        float sdlon = sinf((lon2 - lon1) * 0.5f);
        float a = sdlat * sdlat + cosf(lat1) * cosf(lat2) * sdlon * sdlon;
        a = fminf(fmaxf(a, 0.f), 1.f);
        float d = 2.0f * 6371.0f * asinf(sqrtf(a));
        if (d <= 1.0f)    atomicAdd(&g_counts[0], 1);
        if (d <= 25.0f)   atomicAdd(&g_counts[1], 1);
        if (d <= 200.0f)  atomicAdd(&g_counts[2], 1);
        if (d <= 750.0f)  atomicAdd(&g_counts[3], 1);
        if (d <= 2500.0f) atomicAdd(&g_counts[4], 1);
    }
}

// ============================================================
// Final deterministic reduction -> out[0]=loss, out[1..5]=acc
// ============================================================
__global__ void k_finalize(float* __restrict__ out)
{
    __shared__ float red[256];
    int tid = threadIdx.x;
    float s = 0.f;
    for (int i = tid; i < B; i += 256) s += g_nll[i];
    red[tid] = s; __syncthreads();
    for (int st = 128; st > 0; st >>= 1) {
        if (tid < st) red[tid] += red[tid + st];
        __syncthreads();
    }
    if (tid == 0) out[0] = red[0] / (float)B;
    if (tid < 5)  out[1 + tid] = (float)g_counts[tid] / (float)B;
}

// ============================================================
extern "C" void kernel_launch(void* const* d_in, const int* in_sizes, int n_in,
                              void* d_out, int out_size)
{
    const float* features = (const float*)d_in[0];
    const float* labels   = (const float*)d_in[1];
    const float* cpart    = (const float*)d_in[2];
    const float* mpart    = (const float*)d_in[3];
    const float* fpart    = (const float*)d_in[4];
    const int*   mparents = (const int*)d_in[5];
    const int*   fparents = (const int*)d_in[6];
    const float* cw = (const float*)d_in[7];
    const float* cb = (const float*)d_in[8];
    const float* mw = (const float*)d_in[9];
    const float* mb = (const float*)d_in[10];
    const float* fw = (const float*)d_in[11];
    const float* fb = (const float*)d_in[12];
    float* out = (float*)d_out;

    static cudaStream_t s2 = nullptr;
    static cudaEvent_t evFork = nullptr, evA = nullptr, evJoin = nullptr;
    static cudaEvent_t evG0 = nullptr, evT0 = nullptr;
    static int s_init_done = 0;
    if (!s_init_done) {
        cudaFuncSetAttribute(k_mmagemm, cudaFuncAttributeMaxDynamicSharedMemorySize,
                             GEMM_SMEM);
        cudaFuncSetAttribute(k_tail, cudaFuncAttributeMaxDynamicSharedMemorySize,
                             TAIL_SMEM);
        cudaStreamCreateWithFlags(&s2, cudaStreamNonBlocking);
        cudaEventCreateWithFlags(&evFork, cudaEventDisableTiming);
        cudaEventCreateWithFlags(&evA, cudaEventDisableTiming);
        cudaEventCreateWithFlags(&evJoin, cudaEventDisableTiming);
        cudaEventCreateWithFlags(&evG0, cudaEventDisableTiming);
        cudaEventCreateWithFlags(&evT0, cudaEventDisableTiming);
        s_init_done = 1;
    }

    // fork: convA + init + labelidx on s2, overlapping convW on default
    cudaEventRecord(evFork, 0);
    cudaStreamWaitEvent(s2, evFork, 0);
    k_convA<<<((B * D) / 4 + 255) / 256, 256, 0, s2>>>((const float4*)features);
    cudaEventRecord(evA, s2);
    k_init<<<(NTOT + 255) / 256, 256, 0, s2>>>(labels, cpart, mpart, fpart);
    k_labelidx<<<(3 * B + 7) / 8, 256, 0, s2>>>();
    cudaEventRecord(evJoin, s2);

    k_convW<<<dim3(D / 64, NPTOT / 64), 256>>>(cw, mw, fw);
    cudaStreamWaitEvent(0, evA, 0);      // GEMM needs g_A_hi
    k_mmagemm<<<GRID_MH * GRID_N, 256, GEMM_SMEM>>>(cb, mb, fb, 0);
    cudaEventRecord(evG0, 0);
    k_mmagemm<<<GRID_MH * GRID_N, 256, GEMM_SMEM>>>(cb, mb, fb, B / 2);

    // tail half 0 on s2 (after labelidx in-stream + gemm half 0)
    cudaStreamWaitEvent(s2, evG0, 0);
    k_tail<<<B / 2, TAIL_T, TAIL_SMEM, s2>>>(labels, fpart, fparents, mparents, 0);
    cudaEventRecord(evT0, s2);

    // tail half 1 on default (after gemm half 1 in-stream + init/labelidx)
    cudaStreamWaitEvent(0, evJoin, 0);
    k_tail<<<B / 2, TAIL_T, TAIL_SMEM>>>(labels, fpart, fparents, mparents, B / 2);
    cudaStreamWaitEvent(0, evT0, 0);
    k_finalize<<<1, 256>>>(out);
}